// round 2
// baseline (speedup 1.0000x reference)
#include <cuda_runtime.h>

// Pair_83811991814342: out[(i*512+j)] = concat(x[i], x[j], inter/area_i, inter/area_j)
// n = 512, d = 260, out rows of 522 floats. HBM-store-bound (~547 MB writes).
//
// Strategy: block tiles TI=4 i-rows x TJ=32 j-rows staged in SMEM (kills L2
// read amplification). One warp owns a (i, 16-j) strip; per output row it
// issues 9 unrolled STG.64, with the x[i] half held in registers (no loads).

#define DD      260
#define DD2     130          // float2 per input row
#define ROWLEN  522          // 2*D + 2 floats per output row
#define TI      4
#define TJ      32
#define NTHREADS 256

__global__ __launch_bounds__(NTHREADS, 1)
void pair_kernel(const float* __restrict__ in, float* __restrict__ out, int n)
{
    __shared__ float  xi[TI][DD];
    __shared__ float  xj[TJ][DD];
    __shared__ float2 r12[TI][TJ];

    const int tid = threadIdx.x;
    const int i0  = blockIdx.y * TI;
    const int j0  = blockIdx.x * TJ;

    // ---- Phase 1: cooperative float4 copy of tiles into SMEM ----
    {
        const float4* gi = (const float4*)(in + (size_t)i0 * DD);
        float4*       si = (float4*)&xi[0][0];
        #pragma unroll
        for (int t = tid; t < TI * DD / 4; t += NTHREADS) si[t] = gi[t];

        const float4* gj = (const float4*)(in + (size_t)j0 * DD);
        float4*       sj = (float4*)&xj[0][0];
        for (int t = tid; t < TJ * DD / 4; t += NTHREADS) sj[t] = gj[t];
    }
    __syncthreads();

    // ---- Phase 2: precompute (r1, r2) for all TI x TJ pairs ----
    if (tid < TI * TJ) {
        const int ii = tid / TJ;
        const int jj = tid % TJ;
        const float x1i = xi[ii][256], y1i = xi[ii][257];
        const float x2i = xi[ii][258], y2i = xi[ii][259];
        const float x1j = xj[jj][256], y1j = xj[jj][257];
        const float x2j = xj[jj][258], y2j = xj[jj][259];
        const float ai = (x2i - x1i) * (y2i - y1i);
        const float aj = (x2j - x1j) * (y2j - y1j);
        const float w  = fmaxf(0.0f, fminf(x2i, x2j) - fmaxf(x1i, x1j));
        const float h  = fmaxf(0.0f, fminf(y2i, y2j) - fmaxf(y1i, y1j));
        const float inter = w * h;
        r12[ii][jj] = make_float2(inter / ai, inter / aj);
    }
    __syncthreads();

    // ---- Phase 3: warp-per-row streaming stores ----
    const int wrp  = tid >> 5;
    const int lane = tid & 31;
    const int il   = wrp >> 1;        // 0..3  (local i)
    const int jh   = wrp & 1;         // 0/1   (j half: 16 rows each)

    // Hoist the x[i] half of each row into registers (constant across j).
    const float2* xi2 = (const float2*)&xi[il][0];
    const float2 v0 = xi2[lane];
    const float2 v1 = xi2[lane + 32];
    const float2 v2 = xi2[lane + 64];
    const float2 v3 = xi2[lane + 96];
    // m=4 covers float2 index c = lane+128; c<130 (i.e. lane<2) is still x[i].
    const float2 v4 = xi2[(lane < 2) ? (lane + 128) : 128];

    const int jbase = jh * 16;
    #pragma unroll 4
    for (int r = 0; r < 16; ++r) {
        const int jj = jbase + r;
        const size_t rowbase = ((size_t)(i0 + il) * (size_t)n + (size_t)(j0 + jj))
                               * (size_t)ROWLEN;
        float2* o = (float2*)(out + rowbase);          // rowbase is even -> 8B aligned
        const float2* xj2 = (const float2*)&xj[jj][0];

        // c = lane + 32*m ; c<130 -> x[i], c<260 -> x[j], c==260 -> (r1,r2)
        o[lane      ] = v0;
        o[lane +  32] = v1;
        o[lane +  64] = v2;
        o[lane +  96] = v3;
        {
            const float2 a = xj2[(lane < 2) ? 0 : (lane - 2)];
            o[lane + 128] = (lane < 2) ? v4 : a;       // c = 128..159
        }
        o[lane + 160] = xj2[lane + 30];                // c = 160..191
        o[lane + 192] = xj2[lane + 62];                // c = 192..223
        o[lane + 224] = xj2[lane + 94];                // c = 224..255
        if (lane < 5) {                                // c = 256..260
            const float2 tail = (lane < 4) ? xj2[lane + 126] : r12[il][jj];
            o[lane + 256] = tail;
        }
    }
}

extern "C" void kernel_launch(void* const* d_in, const int* in_sizes, int n_in,
                              void* d_out, int out_size)
{
    const float* in  = (const float*)d_in[0];
    float*       out = (float*)d_out;

    // inputs: (1, 2n, D) fp32 ; n = 512 for this problem
    const int n = (in_sizes[0] / DD) / 2;

    dim3 grid(n / TJ, n / TI);   // (16, 128) = 2048 blocks
    pair_kernel<<<grid, NTHREADS>>>(in, out, n);
}